// round 3
// baseline (speedup 1.0000x reference)
#include <cuda_runtime.h>
#include <cuda_bf16.h>
#include <cstdint>

// Problem constants (SimpleGRU_11974368821377)
#define BB     4096
#define TT     256
#define IND    64
#define HH     20
#define G3     60          // 3*HH
#define NROWS  (BB * TT)   // 1,048,576

typedef unsigned long long ull;

// ---------------------------------------------------------------------------
// Scratch, ROW-MAJOR: g_gx[row][g] = (x[row,:] @ W_ih^T + b_ih)[g], fp32.
// row = b*TT + t.  Row-major keeps K2's per-step gate loads contiguous
// (20 floats/gate => ~2 L1tex wavefronts per LDG instead of 20).
// +64 pad: K2 software-prefetches one step past the end for the last warp.
// ---------------------------------------------------------------------------
__device__ __align__(16) float g_gx[(size_t)NROWS * G3 + 64];

// ---------------------------------------------------------------------------
// f32x2 packed helpers (sm_103a FFMA2 — reachable only via PTX)
// ---------------------------------------------------------------------------
__device__ __forceinline__ void ffma2(ull& d, ull a, ull b) {
    asm("fma.rn.f32x2 %0, %1, %2, %0;" : "+l"(d) : "l"(a), "l"(b));
}
__device__ __forceinline__ ull fadd2(ull a, ull b) {
    ull r; asm("add.rn.f32x2 %0, %1, %2;" : "=l"(r) : "l"(a), "l"(b)); return r;
}
__device__ __forceinline__ ull pack_dup(float w) {
    ull r; unsigned wi = __float_as_uint(w);
    asm("mov.b64 %0, {%1, %2};" : "=l"(r) : "r"(wi), "r"(wi));
    return r;
}

// ---------------------------------------------------------------------------
// Kernel 1: input projection GEMM  [1M, 64] x [64, 60] -> g_gx [1M][60]
//   96 threads = 16 (tx: rows tx+16*rr, rr<8) x 6 (ty: g-block ty*10..+9).
//   Pair dimension = g: acc[rr][j] holds (g0+2j, g0+2j+1) of one row, so
//   each accumulator stores as ONE aligned STG.64 into the row-major scratch.
//   W pairs via LDS.64 (even pitch 62); x scalar LDS + mov.b64 duplicate.
//   40 FFMA2 per k per thread.  Rows/block: 128.  Grid: 8192.
// ---------------------------------------------------------------------------
#define K1_THREADS 96
#define ROWS_PB    128
#define XP         129     // odd pitch: conflict-free transpose store & read
#define WP         62      // even pitch: aligned LDS.64 on g-pairs

__global__ __launch_bounds__(K1_THREADS)
void gru_proj_kernel(const float* __restrict__ x,
                     const float* __restrict__ W_ih,
                     const float* __restrict__ b_ih)
{
    __shared__ float sxT[IND][XP];                 // x tile transposed [k][row]
    __shared__ __align__(8) float sW[IND][WP];     // W^T [k][g]

    const int tid  = threadIdx.x;
    const int row0 = blockIdx.x * ROWS_PB;

    // W_ih (60x64 row-major) -> sW[k][g]
    for (int i = tid; i < G3 * IND; i += K1_THREADS) {
        int g = i >> 6, k = i & 63;
        sW[k][g] = W_ih[i];
    }
    // x tile: coalesced read [row][k], transposed store [k][row] (pitch 129
    // => banks (k+r)%32 across a warp: conflict-free).
    for (int i = tid; i < ROWS_PB * IND; i += K1_THREADS) {
        int r = i >> 6, k = i & 63;
        sxT[k][r] = x[(size_t)(row0 + r) * IND + k];
    }
    __syncthreads();

    const int tx = tid & 15;
    const int ty = tid >> 4;          // 0..5
    const int g0 = ty * 10;

    ull acc[8][5];
#pragma unroll
    for (int rr = 0; rr < 8; rr++)
#pragma unroll
        for (int j = 0; j < 5; j++) acc[rr][j] = 0ull;

#pragma unroll 4
    for (int k = 0; k < IND; k++) {
        ull wv[5];
#pragma unroll
        for (int j = 0; j < 5; j++)
            wv[j] = *reinterpret_cast<const ull*>(&sW[k][g0 + 2 * j]);

        ull xd[8];
#pragma unroll
        for (int rr = 0; rr < 8; rr++)
            xd[rr] = pack_dup(sxT[k][tx + 16 * rr]);

#pragma unroll
        for (int rr = 0; rr < 8; rr++)
#pragma unroll
            for (int j = 0; j < 5; j++)
                ffma2(acc[rr][j], xd[rr], wv[j]);
    }

    // Bias pairs (b_ih global, 8B-aligned at g0 since g0*4 = ty*40).
    ull bias[5];
#pragma unroll
    for (int j = 0; j < 5; j++)
        bias[j] = *reinterpret_cast<const ull*>(&b_ih[g0 + 2 * j]);

#pragma unroll
    for (int rr = 0; rr < 8; rr++) {
        float* orow = g_gx + (size_t)(row0 + tx + 16 * rr) * G3;
#pragma unroll
        for (int j = 0; j < 5; j++)
            *reinterpret_cast<ull*>(&orow[g0 + 2 * j]) = fadd2(acc[rr][j], bias[j]);
    }
}

// ---------------------------------------------------------------------------
// Kernel 2: GRU recurrence + head.  One warp per batch element.
//   Lane l (<20) owns h_l and W_hh rows {l, 20+l, 40+l} in registers.
//   Per-step gate loads are 20 contiguous floats (row-major scratch).
//   One-step software prefetch hides DRAM/L2 latency.
// ---------------------------------------------------------------------------
__device__ __forceinline__ float fast_sigmoid(float v) {
    return __fdividef(1.f, 1.f + __expf(-v));
}
__device__ __forceinline__ float fast_tanh(float v) {
    float s = __fdividef(1.f, 1.f + __expf(-2.f * v));
    return fmaf(2.f, s, -1.f);
}

__global__ __launch_bounds__(128)
void gru_rec_kernel(const float* __restrict__ W_hh,
                    const float* __restrict__ b_hh,
                    const float* __restrict__ W_head,
                    const float* __restrict__ b_head,
                    float* __restrict__ out)
{
    const int warp = (blockIdx.x * blockDim.x + threadIdx.x) >> 5;
    const int lane = threadIdx.x & 31;
    if (warp >= BB) return;

    // Lanes >= 20 mirror lane 0 (keeps all 32 lanes active for shfl).
    const int l = (lane < HH) ? lane : 0;

    float Wr[HH], Wz[HH], Wn[HH];
#pragma unroll
    for (int j = 0; j < HH; j++) {
        Wr[j] = W_hh[(0 * HH + l) * HH + j];
        Wz[j] = W_hh[(1 * HH + l) * HH + j];
        Wn[j] = W_hh[(2 * HH + l) * HH + j];
    }
    const float bhr = b_hh[l], bhz = b_hh[HH + l], bhn = b_hh[2 * HH + l];

    const float* __restrict__ p = g_gx + (size_t)warp * TT * G3;

    // Prime the pipeline: step-0 gate inputs.
    float xr = p[l], xz = p[HH + l], xn = p[2 * HH + l];
    float h = 0.f;

#pragma unroll 2
    for (int t = 0; t < TT; t++) {
        // Prefetch step t+1 (pad at end of g_gx makes the last read safe).
        const float* q = p + (t + 1) * G3;
        const float nxr = q[l];
        const float nxz = q[HH + l];
        const float nxn = q[2 * HH + l];

        float hr = bhr, hz = bhz, hn = bhn;
#pragma unroll
        for (int j = 0; j < HH; j++) {
            const float hj = __shfl_sync(0xFFFFFFFFu, h, j);
            hr = fmaf(Wr[j], hj, hr);
            hz = fmaf(Wz[j], hj, hz);
            hn = fmaf(Wn[j], hj, hn);
        }

        const float r = fast_sigmoid(xr + hr);
        const float z = fast_sigmoid(xz + hz);
        const float n = fast_tanh(fmaf(r, hn, xn));
        h = fmaf(z, h - n, n);   // (1-z)*n + z*h

        xr = nxr; xz = nxz; xn = nxn;
    }

    // Head: out[b] = sum_l h_l * W_head[l] + b_head
    float pv = (lane < HH) ? h * W_head[l] : 0.f;
#pragma unroll
    for (int off = 16; off > 0; off >>= 1)
        pv += __shfl_down_sync(0xFFFFFFFFu, pv, off);
    if (lane == 0) out[warp] = pv + b_head[0];
}

// ---------------------------------------------------------------------------
// Launch
// ---------------------------------------------------------------------------
extern "C" void kernel_launch(void* const* d_in, const int* in_sizes, int n_in,
                              void* d_out, int out_size)
{
    const float* x      = (const float*)d_in[0];
    const float* W_ih   = (const float*)d_in[1];
    const float* W_hh   = (const float*)d_in[2];
    const float* b_ih   = (const float*)d_in[3];
    const float* b_hh   = (const float*)d_in[4];
    const float* W_head = (const float*)d_in[5];
    const float* b_head = (const float*)d_in[6];
    float* out = (float*)d_out;

    gru_proj_kernel<<<NROWS / ROWS_PB, K1_THREADS>>>(x, W_ih, b_ih);
    gru_rec_kernel<<<(BB * 32) / 128, 128>>>(W_hh, b_hh, W_head, b_head, out);
}

// round 12
// speedup vs baseline: 1.7467x; 1.7467x over previous
#include <cuda_runtime.h>
#include <cuda_bf16.h>
#include <cstdint>

// Problem constants (SimpleGRU_11974368821377)
#define BB     4096
#define TT     256
#define IND    64
#define HH     20
#define G3     60          // 3*HH
#define NROWS  (BB * TT)   // 1,048,576

typedef unsigned long long ull;

// ---------------------------------------------------------------------------
// Scratch, ROW-MAJOR: g_gx[row][g], row = b*TT + t.  +64 pad for the K2
// one-step-ahead prefetch.
// ---------------------------------------------------------------------------
__device__ __align__(16) float g_gx[(size_t)NROWS * G3 + 64];

// ---------------------------------------------------------------------------
// f32x2 packed helpers (sm_103a FFMA2 — reachable only via PTX)
// ---------------------------------------------------------------------------
__device__ __forceinline__ void ffma2(ull& d, ull a, ull b) {
    asm("fma.rn.f32x2 %0, %1, %2, %0;" : "+l"(d) : "l"(a), "l"(b));
}
__device__ __forceinline__ ull fadd2(ull a, ull b) {
    ull r; asm("add.rn.f32x2 %0, %1, %2;" : "=l"(r) : "l"(a), "l"(b)); return r;
}
__device__ __forceinline__ ull pack2(float lo, float hi) {
    ull r; unsigned a = __float_as_uint(lo), b = __float_as_uint(hi);
    asm("mov.b64 %0, {%1, %2};" : "=l"(r) : "r"(a), "r"(b));
    return r;
}
__device__ __forceinline__ ull pack_dup(float w) { return pack2(w, w); }
__device__ __forceinline__ float lo32(ull v) {
    unsigned a, b; asm("mov.b64 {%0, %1}, %2;" : "=r"(a), "=r"(b) : "l"(v));
    return __uint_as_float(a);
}
__device__ __forceinline__ float hi32(ull v) {
    unsigned a, b; asm("mov.b64 {%0, %1}, %2;" : "=r"(a), "=r"(b) : "l"(v));
    return __uint_as_float(b);
}

// ---------------------------------------------------------------------------
// Kernel 1: input projection GEMM  [1M, 64] x [64, 60] -> g_gx [1M][60]
//   128 threads = 16 tx (4 rows each) x 8 ty (8 g each = 4 f32x2 pairs).
//   64 rows/block, grid 16384.  G padded to 64 in smem; pad pairs skipped at
//   store.  Per k per thread: 4 LDS(x) + 4 dup-MOV + 4 LDS.64(W) + 16 FFMA2.
//   smem 33.5 KB -> 6 blocks/SM (24 warps, all 4 SMSPs fed).
// ---------------------------------------------------------------------------
#define K1_THREADS 128
#define ROWS_PB    64
#define XP         65      // odd pitch: conflict-free transpose store & read
#define WP         66      // even pitch: aligned LDS.64 on even-g pairs

__global__ __launch_bounds__(K1_THREADS)
void gru_proj_kernel(const float* __restrict__ x,
                     const float* __restrict__ W_ih,
                     const float* __restrict__ b_ih)
{
    __shared__ float sxT[IND][XP];                 // x tile transposed [k][row]
    __shared__ __align__(8) float sW[IND][WP];     // W^T [k][g], g padded to 64

    const int tid  = threadIdx.x;
    const int row0 = blockIdx.x * ROWS_PB;

    // Zero the pad columns g = 60..63.
    for (int i = tid; i < IND * 4; i += K1_THREADS)
        sW[i >> 2][G3 + (i & 3)] = 0.f;
    // W_ih (60x64 row-major) -> sW[k][g].
    for (int i = tid; i < G3 * IND; i += K1_THREADS) {
        int g = i >> 6, k = i & 63;
        sW[k][g] = W_ih[i];
    }
    // x tile: coalesced read [row][k], transposed store [k][row]
    // (pitch 65: store banks k*65+r ≡ k+r mod 32 across a warp — conflict-free).
    for (int i = tid; i < ROWS_PB * IND; i += K1_THREADS) {
        int r = i >> 6, k = i & 63;
        sxT[k][r] = x[(size_t)(row0 + r) * IND + k];
    }
    __syncthreads();

    const int tx = tid & 15;          // rows tx + 16*rr, rr < 4
    const int ty = tid >> 4;          // 0..7, g block ty*8 .. ty*8+7
    const int g0 = ty * 8;

    ull acc[4][4];
#pragma unroll
    for (int rr = 0; rr < 4; rr++)
#pragma unroll
        for (int j = 0; j < 4; j++) acc[rr][j] = 0ull;

#pragma unroll 8
    for (int k = 0; k < IND; k++) {
        ull wv[4];
#pragma unroll
        for (int j = 0; j < 4; j++)
            wv[j] = *reinterpret_cast<const ull*>(&sW[k][g0 + 2 * j]);

        ull xd[4];
#pragma unroll
        for (int rr = 0; rr < 4; rr++)
            xd[rr] = pack_dup(sxT[k][tx + 16 * rr]);

#pragma unroll
        for (int rr = 0; rr < 4; rr++)
#pragma unroll
            for (int j = 0; j < 4; j++)
                ffma2(acc[rr][j], xd[rr], wv[j]);
    }

    // Bias pairs (pair (g,g+1) with even g < 60 stays in-bounds).
    ull bias[4];
#pragma unroll
    for (int j = 0; j < 4; j++) {
        int g = g0 + 2 * j;
        bias[j] = (g < G3) ? *reinterpret_cast<const ull*>(&b_ih[g]) : 0ull;
    }

#pragma unroll
    for (int rr = 0; rr < 4; rr++) {
        float* orow = g_gx + (size_t)(row0 + tx + 16 * rr) * G3;
#pragma unroll
        for (int j = 0; j < 4; j++) {
            int g = g0 + 2 * j;
            if (g < G3)
                *reinterpret_cast<ull*>(&orow[g]) = fadd2(acc[rr][j], bias[j]);
        }
    }
}

// ---------------------------------------------------------------------------
// Kernel 2: GRU recurrence + head.  Block-cooperative:
//   128 threads = 6 batches x 20 hidden units (+1 dummy slot for the 8
//   leftover threads; they run the full loop on slot 6, never store out).
//   h broadcast through smem, stored PRE-DUPLICATED as (h,h) 8B pairs so the
//   r/z gates run as one packed FFMA2 stream with a single LDS.64 per j.
//   Double-buffered h => one __syncthreads per step.
// ---------------------------------------------------------------------------
#define BPB    6                       // real batches per block
#define SLOTS  (BPB + 1)               // + dummy slot
#define K2_THREADS 128

__device__ __forceinline__ float fast_sigmoid(float v) {
    return __fdividef(1.f, 1.f + __expf(-v));
}
__device__ __forceinline__ float fast_tanh(float v) {
    float s = __fdividef(1.f, 1.f + __expf(-2.f * v));
    return fmaf(2.f, s, -1.f);
}

__global__ __launch_bounds__(K2_THREADS)
void gru_rec_kernel(const float* __restrict__ W_hh,
                    const float* __restrict__ b_hh,
                    const float* __restrict__ W_head,
                    const float* __restrict__ b_head,
                    float* __restrict__ out)
{
    __shared__ ull   h_dup[2][SLOTS * HH];   // duplicated h, double-buffered
    __shared__ float red[SLOTS * HH];        // head reduction scratch

    const int tid = threadIdx.x;
    const int bl  = tid / HH;                // 0..6 (6 = dummy)
    const int l   = tid - bl * HH;           // 0..19
    const int b   = blockIdx.x * BPB + bl;   // global batch (may exceed BB)
    const int b_ld = (b < BB) ? b : (BB - 1);

    // Full-range init of BOTH h buffers (covers dummy-slot tail 128..139,
    // which is read every step but only written for indices == tid).
    for (int i = tid; i < SLOTS * HH; i += K2_THREADS) {
        h_dup[0][i] = 0ull;
        h_dup[1][i] = 0ull;
    }

    // Per-unit weights: (Wr[j], Wz[j]) packed; Wn scalar.  ~60 regs.
    ull   Wrz[HH];
    float Wn[HH];
#pragma unroll
    for (int j = 0; j < HH; j++) {
        Wrz[j] = pack2(W_hh[(0 * HH + l) * HH + j],
                       W_hh[(1 * HH + l) * HH + j]);
        Wn[j]  = W_hh[(2 * HH + l) * HH + j];
    }
    const ull   brz = pack2(b_hh[l], b_hh[HH + l]);
    const float bhn = b_hh[2 * HH + l];

    const float* __restrict__ p = g_gx + (size_t)b_ld * TT * G3;

    // Prime step-0 gate inputs.
    float xr = p[l], xz = p[HH + l], xn = p[2 * HH + l];
    float h = 0.f;
    __syncthreads();

    int buf = 0;
#pragma unroll 2
    for (int t = 0; t < TT; t++) {
        // Prefetch step t+1 (tail pad in g_gx keeps the last read in-bounds).
        const float* q = p + (t + 1) * G3;
        const float nxr = q[l];
        const float nxz = q[HH + l];
        const float nxn = q[2 * HH + l];

        ull   arz = brz;     // (hr, hz) packed
        float hn  = bhn;
        const ull* __restrict__ hrow = &h_dup[buf][bl * HH];
#pragma unroll
        for (int j = 0; j < HH; j++) {
            const ull hd = hrow[j];          // (h_j, h_j)
            ffma2(arz, Wrz[j], hd);
            hn = fmaf(Wn[j], lo32(hd), hn);
        }

        const float r = fast_sigmoid(xr + lo32(arz));
        const float z = fast_sigmoid(xz + hi32(arz));
        const float n = fast_tanh(fmaf(r, hn, xn));
        h = fmaf(z, h - n, n);               // (1-z)*n + z*h

        buf ^= 1;
        h_dup[buf][bl * HH + l] = pack_dup(h);
        __syncthreads();

        xr = nxr; xz = nxz; xn = nxn;
    }

    // Head: out[b] = sum_l h_l * W_head[l] + b_head  (reduce across threads)
    red[bl * HH + l] = h * W_head[l];
    __syncthreads();
    if (l == 0 && bl < BPB && b < BB) {
        float s = b_head[0];
#pragma unroll
        for (int j = 0; j < HH; j++) s += red[bl * HH + j];
        out[b] = s;
    }
}

// ---------------------------------------------------------------------------
// Launch
// ---------------------------------------------------------------------------
extern "C" void kernel_launch(void* const* d_in, const int* in_sizes, int n_in,
                              void* d_out, int out_size)
{
    const float* x      = (const float*)d_in[0];
    const float* W_ih   = (const float*)d_in[1];
    const float* W_hh   = (const float*)d_in[2];
    const float* b_ih   = (const float*)d_in[3];
    const float* b_hh   = (const float*)d_in[4];
    const float* W_head = (const float*)d_in[5];
    const float* b_head = (const float*)d_in[6];
    float* out = (float*)d_out;

    gru_proj_kernel<<<NROWS / ROWS_PB, K1_THREADS>>>(x, W_ih, b_ih);

    const int nblk = (BB + BPB - 1) / BPB;   // 683
    gru_rec_kernel<<<nblk, K2_THREADS>>>(W_hh, b_hh, W_head, b_head, out);
}